// round 5
// baseline (speedup 1.0000x reference)
#include <cuda_runtime.h>
#include <cuda_bf16.h>
#include <cstdint>

// Problem constants
#define BATCH 16
#define TT    8192
#define HH    256
#define HQ    64
#define KSLOT 128
#define NTILES (BATCH * (TT / 64))      // 2048 tiles of 64 tokens
#define NB1   (TT / 16)                 // 512 fine blocks (16 tokens)
#define NSB   (TT / 256)                // 32 superblocks (256 tokens)
#define SROWA 260                       // fp32 words per smem row (pad 4)
#define XT_WORDS (64 * SROWA)
#define EXROW 20                        // exchange slot stride (words) -> conflict-free STS.128

// Scratch
__device__ float d_e [BATCH * TT];            // exp(score) per token
__device__ float d_S [BATCH * NB1 * HH];      // 16-token block sums of e*x
__device__ float d_E [BATCH * NB1];           // 16-token block sums of e
__device__ float d_S2[BATCH * NSB * HH];      // 256-token superblock sums
__device__ float d_E2[BATCH * NSB];

__device__ __forceinline__ float tf32r(float x) {
    float r; asm("cvt.rna.tf32.f32 %0, %1;" : "=f"(r) : "f"(x)); return r;
}
__device__ __forceinline__ float tanha(float x) {
    float r; asm("tanh.approx.f32 %0, %1;" : "=f"(r) : "f"(x)); return r;
}
__device__ __forceinline__ void cpa16(uint32_t dst, const float* src) {
    asm volatile("cp.async.cg.shared.global [%0], [%1], 16;" :: "r"(dst), "l"(src));
}

// smem: sX[2][64][SROWA] | sE[64] | sP[64][4] | sEx[8*32*EXROW]
#define SMEM_A_WORDS (2 * XT_WORDS + 64 + 64 * 4 + 8 * 32 * EXROW)
#define SMEM_A_BYTES (SMEM_A_WORDS * 4)

__global__ void __launch_bounds__(512, 1) pass_a_kernel(
    const float* __restrict__ x,
    const float* __restrict__ W1,
    const float* __restrict__ b1,
    const float* __restrict__ W2,
    const float* __restrict__ b2)
{
    extern __shared__ float sm[];
    float* sXbuf[2] = { sm, sm + XT_WORDS };
    float* sE  = sm + 2 * XT_WORDS;
    float* sP  = sE + 64;
    float* sEx = sP + 64 * 4;

    const int tid  = threadIdx.x;
    const int warp = tid >> 5;           // 0..15
    const int lane = tid & 31;
    const int g    = lane >> 2;          // 0..7
    const int q    = lane & 3;           // 0..3
    const int kh   = warp >> 3;          // K half: 0 -> k 0..127, 1 -> 128..255
    const int half = (warp >> 2) & 1;    // token half: rows half*32 ..
    const int nq   = warp & 3;           // n quarter: cols [nq*16, nq*16+16)
    const int ew   = warp & 7;           // exchange pairing id (same half,nq across kh)

    uint32_t smem_u32;
    { uint64_t t64; asm("cvta.to.shared.u64 %0, %1;" : "=l"(t64) : "l"(sm));
      smem_u32 = (uint32_t)t64; }

    // --- W1 register-resident B fragments for this warp's K half ---
    uint32_t Breg[16][2][2];
    #pragma unroll
    for (int kt = 0; kt < 16; kt++)
        #pragma unroll
        for (int nt = 0; nt < 2; nt++) {
            const int n = nq * 16 + nt * 8 + g;
            const int k = kh * 128 + kt * 8 + q;
            Breg[kt][nt][0] = __float_as_uint(tf32r(W1[(k)     * HQ + n]));
            Breg[kt][nt][1] = __float_as_uint(tf32r(W1[(k + 4) * HQ + n]));
        }

    // Epilogue constants (only kh==0 warps use them)
    float w2c[2][2], b1c[2][2];
    #pragma unroll
    for (int nt = 0; nt < 2; nt++)
        #pragma unroll
        for (int j = 0; j < 2; j++) {
            const int c = nq * 16 + nt * 8 + 2 * q + j;
            w2c[nt][j] = W2[c]; b1c[nt][j] = b1[c];
        }
    const float bb2 = b2[0];

    int tile = blockIdx.x;
    {   // prefetch first tile into buf 0 (512 threads x 8 chunks of 16B)
        const float* src = x + (size_t)tile * (64 * HH);
        #pragma unroll
        for (int i = 0; i < 8; i++) {
            const int off = i * 2048 + tid * 4;
            const int r = off >> 8, c = off & 255;
            cpa16(smem_u32 + (uint32_t)(r * SROWA + c) * 4, src + off);
        }
        asm volatile("cp.async.commit_group;");
    }

    int buf = 0;
    for (; tile < NTILES; tile += gridDim.x, buf ^= 1) {
        float* sX  = sXbuf[buf];
        const int next = tile + gridDim.x;

        __syncthreads();   // prior tile fully consumed (sX other buf, sEx, sE, sP free)

        if (next < NTILES) {
            const float* src = x + (size_t)next * (64 * HH);
            const uint32_t base = smem_u32 + (uint32_t)((buf ^ 1) * XT_WORDS) * 4;
            #pragma unroll
            for (int i = 0; i < 8; i++) {
                const int off = i * 2048 + tid * 4;
                const int r = off >> 8, c = off & 255;
                cpa16(base + (uint32_t)(r * SROWA + c) * 4, src + off);
            }
            asm volatile("cp.async.commit_group;");
            asm volatile("cp.async.wait_group 1;");
        } else {
            asm volatile("cp.async.wait_group 0;");
        }
        __syncthreads();   // current buffer visible

        // --- MMA: warp computes 32 tokens x 16 n-cols over its K half ---
        float acc[2][2][4];
        #pragma unroll
        for (int m = 0; m < 2; m++)
            #pragma unroll
            for (int nt = 0; nt < 2; nt++)
                #pragma unroll
                for (int i = 0; i < 4; i++) acc[m][nt][i] = 0.f;

        const int r0 = half * 32;
        const int kbase = kh * 128;
        #pragma unroll
        for (int kt = 0; kt < 16; kt++) {
            const int kb = kbase + kt * 8 + q;
            #pragma unroll
            for (int m = 0; m < 2; m++) {
                const int rr = r0 + m * 16 + g;
                uint32_t a0 = __float_as_uint(sX[(rr)     * SROWA + kb]);
                uint32_t a1 = __float_as_uint(sX[(rr + 8) * SROWA + kb]);
                uint32_t a2 = __float_as_uint(sX[(rr)     * SROWA + kb + 4]);
                uint32_t a3 = __float_as_uint(sX[(rr + 8) * SROWA + kb + 4]);
                #pragma unroll
                for (int nt = 0; nt < 2; nt++) {
                    asm volatile(
                        "mma.sync.aligned.m16n8k8.row.col.f32.tf32.tf32.f32 "
                        "{%0,%1,%2,%3},{%4,%5,%6,%7},{%8,%9},{%0,%1,%2,%3};"
                        : "+f"(acc[m][nt][0]), "+f"(acc[m][nt][1]),
                          "+f"(acc[m][nt][2]), "+f"(acc[m][nt][3])
                        : "r"(a0), "r"(a1), "r"(a2), "r"(a3),
                          "r"(Breg[kt][nt][0]), "r"(Breg[kt][nt][1]));
                }
            }
        }

        // --- K-half exchange: kh=1 warps ship partials to kh=0 warps ---
        float* slot = sEx + (ew * 32 + lane) * EXROW;
        if (kh == 1) {
            #pragma unroll
            for (int m = 0; m < 2; m++)
                #pragma unroll
                for (int nt = 0; nt < 2; nt++)
                    *(float4*)(slot + (m * 2 + nt) * 4) =
                        make_float4(acc[m][nt][0], acc[m][nt][1],
                                    acc[m][nt][2], acc[m][nt][3]);
        }
        __syncthreads();

        if (kh == 0) {
            // add peer partials + epilogue
            #pragma unroll
            for (int m = 0; m < 2; m++) {
                #pragma unroll
                for (int nt = 0; nt < 2; nt++) {
                    float4 p = *(const float4*)(slot + (m * 2 + nt) * 4);
                    acc[m][nt][0] += p.x; acc[m][nt][1] += p.y;
                    acc[m][nt][2] += p.z; acc[m][nt][3] += p.w;
                }
                const int rr = r0 + m * 16 + g;
                float p0 = 0.f, p1 = 0.f;
                #pragma unroll
                for (int nt = 0; nt < 2; nt++) {
                    p0 += tanha(acc[m][nt][0] + b1c[nt][0]) * w2c[nt][0]
                        + tanha(acc[m][nt][1] + b1c[nt][1]) * w2c[nt][1];
                    p1 += tanha(acc[m][nt][2] + b1c[nt][0]) * w2c[nt][0]
                        + tanha(acc[m][nt][3] + b1c[nt][1]) * w2c[nt][1];
                }
                p0 += __shfl_xor_sync(0xffffffffu, p0, 1);
                p0 += __shfl_xor_sync(0xffffffffu, p0, 2);
                p1 += __shfl_xor_sync(0xffffffffu, p1, 1);
                p1 += __shfl_xor_sync(0xffffffffu, p1, 2);
                if (q == 0) {
                    sP[(rr)     * 4 + nq] = p0;
                    sP[(rr + 8) * 4 + nq] = p1;
                }
            }
        }
        __syncthreads();

        const int b     = tile >> 7;
        const int blk64 = tile & 127;

        if (tid < 64) {
            float s = bb2 + sP[tid * 4] + sP[tid * 4 + 1]
                          + sP[tid * 4 + 2] + sP[tid * 4 + 3];
            const float e = __expf(s);
            sE[tid] = e;
            d_e[b * TT + blk64 * 64 + tid] = e;
        }
        __syncthreads();

        // --- 16-token block partial sums: 512 threads, 2 blocks each ---
        {
            const int h   = tid & 255;
            const int grp = tid >> 8;        // 0: blocks 0,1 ; 1: blocks 2,3
            #pragma unroll
            for (int jj = 0; jj < 2; jj++) {
                const int j = grp * 2 + jj;
                float a = 0.f, den = 0.f;
                #pragma unroll
                for (int t = j * 16; t < j * 16 + 16; t++) {
                    const float e = sE[t];
                    a   += e * sX[t * SROWA + h];
                    den += e;
                }
                const int bi = b * NB1 + blk64 * 4 + j;
                d_S[(size_t)bi * HH + h] = a;
                if (h == 0) d_E[bi] = den;
            }
        }
    }
}

// Aggregate 16 fine blocks -> 1 superblock
__global__ void __launch_bounds__(256) pass_ab_kernel()
{
    const int sb  = blockIdx.x & (NSB - 1);
    const int b   = blockIdx.x >> 5;
    const int tid = threadIdx.x;

    const float* Sb = d_S + ((size_t)(b * NB1 + sb * 16)) * HH + tid;
    float s0 = 0.f, s1 = 0.f, s2 = 0.f, s3 = 0.f;
    #pragma unroll
    for (int i = 0; i < 16; i += 4) {
        s0 += Sb[(size_t)(i + 0) * HH];
        s1 += Sb[(size_t)(i + 1) * HH];
        s2 += Sb[(size_t)(i + 2) * HH];
        s3 += Sb[(size_t)(i + 3) * HH];
    }
    d_S2[(size_t)(b * NSB + sb) * HH + tid] = (s0 + s1) + (s2 + s3);
    if (tid == 0) {
        float e = 0.f;
        #pragma unroll
        for (int i = 0; i < 16; i++) e += d_E[b * NB1 + sb * 16 + i];
        d_E2[b * NSB + sb] = e;
    }
}

__global__ void __launch_bounds__(256) pass_b_kernel(
    const float* __restrict__ x,
    const int*   __restrict__ boundaries,
    const int*   __restrict__ slot_mask,
    float*       __restrict__ out)
{
    const int k   = blockIdx.x;
    const int b   = blockIdx.y;
    const int tid = threadIdx.x;     // h index

    const int sidx  = b * KSLOT + k;
    const int start = boundaries[sidx * 2];
    const int end   = boundaries[sidx * 2 + 1];
    const int mask  = slot_mask[sidx];

    float* o = out + (size_t)sidx * HH;
    if (mask <= 0 || start >= end) { o[tid] = 0.f; return; }

    const float* xb  = x    + (size_t)b * TT * HH;
    const float* eb  = d_e  + b * TT;
    const float* Sb1 = d_S  + (size_t)b * NB1 * HH;
    const float* Eb1 = d_E  + b * NB1;
    const float* Sb2 = d_S2 + (size_t)b * NSB * HH;
    const float* Eb2 = d_E2 + b * NSB;

    float acc = 0.f, den = 0.f;

    auto tokens = [&](int t0, int t1) {
        float ea = 0.f, ec = 0.f, da = 0.f, dc = 0.f;
        int t = t0;
        for (; t + 2 <= t1; t += 2) {
            const float e0 = eb[t], e1 = eb[t + 1];
            ea += e0 * xb[(size_t)(t)     * HH + tid]; da += e0;
            ec += e1 * xb[(size_t)(t + 1) * HH + tid]; dc += e1;
        }
        if (t < t1) { const float e = eb[t]; ea += e * xb[(size_t)t * HH + tid]; da += e; }
        acc += ea + ec; den += da + dc;
    };
    auto blocks = [&](int i0, int i1) {
        float a0 = 0.f, a1 = 0.f, d0 = 0.f, d1 = 0.f;
        int i = i0;
        for (; i + 2 <= i1; i += 2) {
            a0 += Sb1[(size_t)(i)     * HH + tid]; d0 += Eb1[i];
            a1 += Sb1[(size_t)(i + 1) * HH + tid]; d1 += Eb1[i + 1];
        }
        if (i < i1) { a0 += Sb1[(size_t)i * HH + tid]; d0 += Eb1[i]; }
        acc += a0 + a1; den += d0 + d1;
    };

    const int fb = (start + 15) >> 4;
    const int lb = end >> 4;

    if (fb >= lb) {
        tokens(start, end);
    } else {
        tokens(start, fb * 16);
        tokens(lb * 16, end);

        const int fs = (fb + 15) >> 4;
        const int ls = lb >> 4;
        if (fs >= ls) {
            blocks(fb, lb);
        } else {
            blocks(fb, fs * 16);
            blocks(ls * 16, lb);
            float a0 = 0.f, a1 = 0.f, a2 = 0.f, a3 = 0.f;
            float d0 = 0.f, d1 = 0.f, d2 = 0.f, d3 = 0.f;
            int i = fs;
            for (; i + 4 <= ls; i += 4) {
                a0 += Sb2[(size_t)(i + 0) * HH + tid]; d0 += Eb2[i + 0];
                a1 += Sb2[(size_t)(i + 1) * HH + tid]; d1 += Eb2[i + 1];
                a2 += Sb2[(size_t)(i + 2) * HH + tid]; d2 += Eb2[i + 2];
                a3 += Sb2[(size_t)(i + 3) * HH + tid]; d3 += Eb2[i + 3];
            }
            for (; i < ls; i++) { a0 += Sb2[(size_t)i * HH + tid]; d0 += Eb2[i]; }
            acc += (a0 + a1) + (a2 + a3);
            den += (d0 + d1) + (d2 + d3);
        }
    }

    o[tid] = acc / den;   // den > 0: end > start and all e_t > 0
}

extern "C" void kernel_launch(void* const* d_in, const int* in_sizes, int n_in,
                              void* d_out, int out_size)
{
    const float* x          = (const float*)d_in[0];
    const int*   boundaries = (const int*)d_in[1];
    const int*   slot_mask  = (const int*)d_in[2];
    const float* W1         = (const float*)d_in[3];
    const float* b1         = (const float*)d_in[4];
    const float* W2         = (const float*)d_in[5];
    const float* b2         = (const float*)d_in[6];
    float* out = (float*)d_out;

    cudaFuncSetAttribute(pass_a_kernel,
                         cudaFuncAttributeMaxDynamicSharedMemorySize,
                         SMEM_A_BYTES);

    pass_a_kernel<<<148, 512, SMEM_A_BYTES>>>(x, W1, b1, W2, b2);
    pass_ab_kernel<<<BATCH * NSB, 256>>>();
    pass_b_kernel<<<dim3(KSLOT, BATCH), 256>>>(x, boundaries, slot_mask, out);
}

// round 6
// speedup vs baseline: 1.0649x; 1.0649x over previous
#include <cuda_runtime.h>
#include <cuda_bf16.h>
#include <cstdint>

// Problem constants
#define BATCH 16
#define TT    8192
#define HH    256
#define HQ    64
#define KSLOT 128
#define TILE  32                        // tokens per tile
#define NT32  (BATCH * (TT / TILE))     // 4096 tiles
#define NB1   (TT / 16)                 // 512 fine blocks (16 tokens)
#define NSB   (TT / 256)                // 32 superblocks
#define SROWA 260                       // fp32 words per smem row (pad 4)
#define XT_WORDS (TILE * SROWA)         // 8320
#define EXR   36                        // exchange slot stride (words)

// Scratch
__device__ float d_e [BATCH * TT];
__device__ float d_S [BATCH * NB1 * HH];
__device__ float d_E [BATCH * NB1];
__device__ float d_S2[BATCH * NSB * HH];
__device__ float d_E2[BATCH * NSB];

__device__ __forceinline__ float tf32r(float x) {
    float r; asm("cvt.rna.tf32.f32 %0, %1;" : "=f"(r) : "f"(x)); return r;
}
__device__ __forceinline__ float tanha(float x) {
    float r; asm("tanh.approx.f32 %0, %1;" : "=f"(r) : "f"(x)); return r;
}
__device__ __forceinline__ void cpa16(uint32_t dst, const float* src) {
    asm volatile("cp.async.cg.shared.global [%0], [%1], 16;" :: "r"(dst), "l"(src));
}

// smem: sX[2][32][SROWA] | sEx[6*32*EXR] | sE[32] | sP[32*2] | sW2[64] | sB1[64]
#define SMEM_A_WORDS (2 * XT_WORDS + 6 * 32 * EXR + 32 + 64 + 64 + 64)
#define SMEM_A_BYTES (SMEM_A_WORDS * 4)

__global__ void __launch_bounds__(256, 2) pass_a_kernel(
    const float* __restrict__ x,
    const float* __restrict__ W1,
    const float* __restrict__ b1,
    const float* __restrict__ W2,
    const float* __restrict__ b2)
{
    extern __shared__ float sm[];
    float* sXbuf[2] = { sm, sm + XT_WORDS };
    float* sEx = sm + 2 * XT_WORDS;
    float* sE  = sEx + 6 * 32 * EXR;
    float* sP  = sE + 32;
    float* sW2 = sP + 64;
    float* sB1 = sW2 + 64;

    const int tid  = threadIdx.x;
    const int warp = tid >> 5;           // 0..7
    const int lane = tid & 31;
    const int g    = lane >> 2;          // 0..7
    const int q    = lane & 3;           // 0..3
    const int kq   = warp & 3;           // K quarter: k in [kq*64, kq*64+64)
    const int nh   = warp >> 2;          // n half: cols [nh*32, nh*32+32)

    uint32_t smem_u32;
    { uint64_t t64; asm("cvta.to.shared.u64 %0, %1;" : "=l"(t64) : "l"(sm));
      smem_u32 = (uint32_t)t64; }

    // Stage epilogue constants to smem (visible after first loop-top barrier)
    if (tid < 64) { sW2[tid] = W2[tid]; sB1[tid] = b1[tid]; }

    // --- W1 register-resident B fragments: warp covers 64 k x 32 n ---
    uint32_t Breg[8][4][2];
    #pragma unroll
    for (int kt = 0; kt < 8; kt++)
        #pragma unroll
        for (int nt = 0; nt < 4; nt++) {
            const int n = nh * 32 + nt * 8 + g;
            const int k = kq * 64 + kt * 8 + q;
            Breg[kt][nt][0] = __float_as_uint(tf32r(W1[(k)     * HQ + n]));
            Breg[kt][nt][1] = __float_as_uint(tf32r(W1[(k + 4) * HQ + n]));
        }

    int tile = blockIdx.x;
    {   // prefetch first tile into buf 0 (256 thr x 8 chunks of 16B)
        const float* src = x + (size_t)tile * (TILE * HH);
        #pragma unroll
        for (int i = 0; i < 8; i++) {
            const int off = i * 1024 + tid * 4;
            const int r = off >> 8, c = off & 255;
            cpa16(smem_u32 + (uint32_t)(r * SROWA + c) * 4, src + off);
        }
        asm volatile("cp.async.commit_group;");
    }

    int buf = 0;
    for (; tile < NT32; tile += gridDim.x, buf ^= 1) {
        float* sX  = sXbuf[buf];
        const int next = tile + gridDim.x;

        __syncthreads();   // prior tile fully consumed

        if (next < NT32) {
            const float* src = x + (size_t)next * (TILE * HH);
            const uint32_t base = smem_u32 + (uint32_t)((buf ^ 1) * XT_WORDS) * 4;
            #pragma unroll
            for (int i = 0; i < 8; i++) {
                const int off = i * 1024 + tid * 4;
                const int r = off >> 8, c = off & 255;
                cpa16(base + (uint32_t)(r * SROWA + c) * 4, src + off);
            }
            asm volatile("cp.async.commit_group;");
            asm volatile("cp.async.wait_group 1;");
        } else {
            asm volatile("cp.async.wait_group 0;");
        }
        __syncthreads();   // current buffer visible

        // --- MMA: warp computes 32 tokens x 32 n-cols over its K quarter ---
        float acc[2][4][4];
        #pragma unroll
        for (int m = 0; m < 2; m++)
            #pragma unroll
            for (int nt = 0; nt < 4; nt++)
                #pragma unroll
                for (int i = 0; i < 4; i++) acc[m][nt][i] = 0.f;

        #pragma unroll
        for (int kt = 0; kt < 8; kt++) {
            const int kb = kq * 64 + kt * 8 + q;
            #pragma unroll
            for (int m = 0; m < 2; m++) {
                const int rl = m * 16 + g;
                uint32_t a0 = __float_as_uint(sX[(rl)     * SROWA + kb]);
                uint32_t a1 = __float_as_uint(sX[(rl + 8) * SROWA + kb]);
                uint32_t a2 = __float_as_uint(sX[(rl)     * SROWA + kb + 4]);
                uint32_t a3 = __float_as_uint(sX[(rl + 8) * SROWA + kb + 4]);
                #pragma unroll
                for (int nt = 0; nt < 4; nt++) {
                    asm volatile(
                        "mma.sync.aligned.m16n8k8.row.col.f32.tf32.tf32.f32 "
                        "{%0,%1,%2,%3},{%4,%5,%6,%7},{%8,%9},{%0,%1,%2,%3};"
                        : "+f"(acc[m][nt][0]), "+f"(acc[m][nt][1]),
                          "+f"(acc[m][nt][2]), "+f"(acc[m][nt][3])
                        : "r"(a0), "r"(a1), "r"(a2), "r"(a3),
                          "r"(Breg[kt][nt][0]), "r"(Breg[kt][nt][1]));
                }
            }
        }

        // --- K-quarter exchange: kq=1..3 ship partials to kq=0 ---
        if (kq > 0) {
            float* slot = sEx + ((nh * 3 + (kq - 1)) * 32 + lane) * EXR;
            #pragma unroll
            for (int m = 0; m < 2; m++)
                #pragma unroll
                for (int nt = 0; nt < 4; nt++)
                    *(float4*)(slot + (m * 4 + nt) * 4) =
                        make_float4(acc[m][nt][0], acc[m][nt][1],
                                    acc[m][nt][2], acc[m][nt][3]);
        }
        __syncthreads();

        if (kq == 0) {
            #pragma unroll
            for (int peer = 0; peer < 3; peer++) {
                const float* slot = sEx + ((nh * 3 + peer) * 32 + lane) * EXR;
                #pragma unroll
                for (int m = 0; m < 2; m++)
                    #pragma unroll
                    for (int nt = 0; nt < 4; nt++) {
                        float4 p = *(const float4*)(slot + (m * 4 + nt) * 4);
                        acc[m][nt][0] += p.x; acc[m][nt][1] += p.y;
                        acc[m][nt][2] += p.z; acc[m][nt][3] += p.w;
                    }
            }
            // epilogue: tanh + W2-dot -> partial over this nh's 32 cols
            #pragma unroll
            for (int m = 0; m < 2; m++) {
                const int rl = m * 16 + g;
                float p0 = 0.f, p1 = 0.f;
                #pragma unroll
                for (int nt = 0; nt < 4; nt++) {
                    const int c0 = nh * 32 + nt * 8 + 2 * q;
                    const float w0 = sW2[c0], w1 = sW2[c0 + 1];
                    const float bb0 = sB1[c0], bb1 = sB1[c0 + 1];
                    p0 += tanha(acc[m][nt][0] + bb0) * w0
                        + tanha(acc[m][nt][1] + bb1) * w1;
                    p1 += tanha(acc[m][nt][2] + bb0) * w0
                        + tanha(acc[m][nt][3] + bb1) * w1;
                }
                p0 += __shfl_xor_sync(0xffffffffu, p0, 1);
                p0 += __shfl_xor_sync(0xffffffffu, p0, 2);
                p1 += __shfl_xor_sync(0xffffffffu, p1, 1);
                p1 += __shfl_xor_sync(0xffffffffu, p1, 2);
                if (q == 0) {
                    sP[(rl)     * 2 + nh] = p0;
                    sP[(rl + 8) * 2 + nh] = p1;
                }
            }
        }
        __syncthreads();

        const int b     = tile >> 8;         // batch (TT/TILE = 256)
        const int blk32 = tile & 255;

        if (tid < TILE) {
            const float s = b2[0] + sP[tid * 2] + sP[tid * 2 + 1];
            const float e = __expf(s);
            sE[tid] = e;
            d_e[b * TT + blk32 * TILE + tid] = e;
        }
        __syncthreads();

        // --- two 16-token block partial sums, all 256 threads ---
        #pragma unroll
        for (int j = 0; j < 2; j++) {
            float a = 0.f, den = 0.f;
            #pragma unroll
            for (int t = j * 16; t < j * 16 + 16; t++) {
                const float e = sE[t];
                a   += e * sX[t * SROWA + tid];
                den += e;
            }
            const int bi = b * NB1 + blk32 * 2 + j;
            d_S[(size_t)bi * HH + tid] = a;
            if (tid == 0) d_E[bi] = den;
        }
    }
}

// Aggregate 16 fine blocks -> 1 superblock
__global__ void __launch_bounds__(256) pass_ab_kernel()
{
    const int sb  = blockIdx.x & (NSB - 1);
    const int b   = blockIdx.x >> 5;
    const int tid = threadIdx.x;

    const float* Sb = d_S + ((size_t)(b * NB1 + sb * 16)) * HH + tid;
    float s0 = 0.f, s1 = 0.f, s2 = 0.f, s3 = 0.f;
    #pragma unroll
    for (int i = 0; i < 16; i += 4) {
        s0 += Sb[(size_t)(i + 0) * HH];
        s1 += Sb[(size_t)(i + 1) * HH];
        s2 += Sb[(size_t)(i + 2) * HH];
        s3 += Sb[(size_t)(i + 3) * HH];
    }
    d_S2[(size_t)(b * NSB + sb) * HH + tid] = (s0 + s1) + (s2 + s3);
    if (tid == 0) {
        float e = 0.f;
        #pragma unroll
        for (int i = 0; i < 16; i++) e += d_E[b * NB1 + sb * 16 + i];
        d_E2[b * NSB + sb] = e;
    }
}

__global__ void __launch_bounds__(256) pass_b_kernel(
    const float* __restrict__ x,
    const int*   __restrict__ boundaries,
    const int*   __restrict__ slot_mask,
    float*       __restrict__ out)
{
    const int k   = blockIdx.x;
    const int b   = blockIdx.y;
    const int tid = threadIdx.x;     // h index

    const int sidx  = b * KSLOT + k;
    const int start = boundaries[sidx * 2];
    const int end   = boundaries[sidx * 2 + 1];
    const int mask  = slot_mask[sidx];

    float* o = out + (size_t)sidx * HH;
    if (mask <= 0 || start >= end) { o[tid] = 0.f; return; }

    const float* xb  = x    + (size_t)b * TT * HH;
    const float* eb  = d_e  + b * TT;
    const float* Sb1 = d_S  + (size_t)b * NB1 * HH;
    const float* Eb1 = d_E  + b * NB1;
    const float* Sb2 = d_S2 + (size_t)b * NSB * HH;
    const float* Eb2 = d_E2 + b * NSB;

    float acc = 0.f, den = 0.f;

    auto tokens = [&](int t0, int t1) {
        float ea = 0.f, ec = 0.f, da = 0.f, dc = 0.f;
        int t = t0;
        for (; t + 2 <= t1; t += 2) {
            const float e0 = eb[t], e1 = eb[t + 1];
            ea += e0 * xb[(size_t)(t)     * HH + tid]; da += e0;
            ec += e1 * xb[(size_t)(t + 1) * HH + tid]; dc += e1;
        }
        if (t < t1) { const float e = eb[t]; ea += e * xb[(size_t)t * HH + tid]; da += e; }
        acc += ea + ec; den += da + dc;
    };
    auto blocks = [&](int i0, int i1) {
        float a0 = 0.f, a1 = 0.f, d0 = 0.f, d1 = 0.f;
        int i = i0;
        for (; i + 2 <= i1; i += 2) {
            a0 += Sb1[(size_t)(i)     * HH + tid]; d0 += Eb1[i];
            a1 += Sb1[(size_t)(i + 1) * HH + tid]; d1 += Eb1[i + 1];
        }
        if (i < i1) { a0 += Sb1[(size_t)i * HH + tid]; d0 += Eb1[i]; }
        acc += a0 + a1; den += d0 + d1;
    };

    const int fb = (start + 15) >> 4;
    const int lb = end >> 4;

    if (fb >= lb) {
        tokens(start, end);
    } else {
        tokens(start, fb * 16);
        tokens(lb * 16, end);

        const int fs = (fb + 15) >> 4;
        const int ls = lb >> 4;
        if (fs >= ls) {
            blocks(fb, lb);
        } else {
            blocks(fb, fs * 16);
            blocks(ls * 16, lb);
            float a0 = 0.f, a1 = 0.f, a2 = 0.f, a3 = 0.f;
            float d0 = 0.f, d1 = 0.f, d2 = 0.f, d3 = 0.f;
            int i = fs;
            for (; i + 4 <= ls; i += 4) {
                a0 += Sb2[(size_t)(i + 0) * HH + tid]; d0 += Eb2[i + 0];
                a1 += Sb2[(size_t)(i + 1) * HH + tid]; d1 += Eb2[i + 1];
                a2 += Sb2[(size_t)(i + 2) * HH + tid]; d2 += Eb2[i + 2];
                a3 += Sb2[(size_t)(i + 3) * HH + tid]; d3 += Eb2[i + 3];
            }
            for (; i < ls; i++) { a0 += Sb2[(size_t)i * HH + tid]; d0 += Eb2[i]; }
            acc += (a0 + a1) + (a2 + a3);
            den += (d0 + d1) + (d2 + d3);
        }
    }

    o[tid] = acc / den;   // den > 0: end > start and all e_t > 0
}

extern "C" void kernel_launch(void* const* d_in, const int* in_sizes, int n_in,
                              void* d_out, int out_size)
{
    const float* x          = (const float*)d_in[0];
    const int*   boundaries = (const int*)d_in[1];
    const int*   slot_mask  = (const int*)d_in[2];
    const float* W1         = (const float*)d_in[3];
    const float* b1         = (const float*)d_in[4];
    const float* W2         = (const float*)d_in[5];
    const float* b2         = (const float*)d_in[6];
    float* out = (float*)d_out;

    cudaFuncSetAttribute(pass_a_kernel,
                         cudaFuncAttributeMaxDynamicSharedMemorySize,
                         SMEM_A_BYTES);

    pass_a_kernel<<<296, 256, SMEM_A_BYTES>>>(x, W1, b1, W2, b2);
    pass_ab_kernel<<<BATCH * NSB, 256>>>();
    pass_b_kernel<<<dim3(KSLOT, BATCH), 256>>>(x, boundaries, slot_mask, out);
}